// round 4
// baseline (speedup 1.0000x reference)
#include <cuda_runtime.h>
#include <cstdint>

// StreamingSTFT collapses analytically:
//   irfft(rfft(x)) == x  =>  frame = in_buf * aw * sw
//   sw nonzero only on [96,160)  =>  overlap-add reduces to
//   out[i][j] = chunk[i-3][j] * W[j]   (i >= 3), else 0
//   W[j] = aw[j+128]*sw[j+128] (j<32) ; aw[j+64]*sw[j+64] (j>=32)
//
// R3: same plan as R2 (balanced 148*8 grid + L2-resident working set), but
// eviction hint expressed via createpolicy + L2::cache_hint, which ptxas
// accepts on .v4.f32 (the bare .L2::evict_last qualifier needs 32B forms).

static constexpr int HOP = 64;
static constexpr long long NUM_FRAMES = 131072;
static constexpr long long N_ELEMS = NUM_FRAMES * HOP;   // 8,388,608
static constexpr long long N_VEC4  = N_ELEMS / 4;        // 2,097,152
static constexpr int DELAY_VEC4 = (3 * HOP) / 4;         // 48 float4s = 3 rows

static constexpr int NUM_SMS = 148;
static constexpr int BLOCKS  = NUM_SMS * 8;              // 1184
static constexpr int THREADS = 256;
static constexpr int STRIDE  = BLOCKS * THREADS;         // 303104, %16 == 0
static constexpr int ITERS   = 7;                        // ceil(N_VEC4 / STRIDE)

__device__ __forceinline__ uint64_t make_evict_last_policy() {
    uint64_t pol;
    asm volatile("createpolicy.fractional.L2::evict_last.b64 %0, 1.0;"
                 : "=l"(pol));
    return pol;
}

__device__ __forceinline__ float4 ldg_hint(const float4* p, uint64_t pol) {
    float4 v;
    asm volatile("ld.global.nc.L2::cache_hint.v4.f32 {%0,%1,%2,%3}, [%4], %5;"
                 : "=f"(v.x), "=f"(v.y), "=f"(v.z), "=f"(v.w)
                 : "l"(p), "l"(pol));
    return v;
}

__device__ __forceinline__ void stg_hint(float4* p, float4 v, uint64_t pol) {
    asm volatile("st.global.L2::cache_hint.v4.f32 [%0], {%1,%2,%3,%4}, %5;"
                 :: "l"(p), "f"(v.x), "f"(v.y), "f"(v.z), "f"(v.w), "l"(pol)
                 : "memory");
}

__global__ void __launch_bounds__(THREADS)
stft_delay_scale_kernel(const float4* __restrict__ chunk4,
                        const float*  __restrict__ aw,
                        const float*  __restrict__ sw,
                        float4* __restrict__ out4)
{
    const int i0 = blockIdx.x * THREADS + threadIdx.x;
    const uint64_t pol = make_evict_last_policy();

    // Column of this lane within the 64-wide row; invariant across the
    // strided loop because STRIDE % 16 == 0.
    const int j0   = (i0 & 15) << 2;
    const int base = j0 + (j0 < 32 ? 128 : 64);           // float4-aligned

    const float4 a = *reinterpret_cast<const float4*>(aw + base);
    const float4 s = *reinterpret_cast<const float4*>(sw + base);
    const float4 w = make_float4(a.x * s.x, a.y * s.y, a.z * s.z, a.w * s.w);

    // Front-batch the independent loads (MLP up to 7).
    float4 v[ITERS];
#pragma unroll
    for (int k = 0; k < ITERS; k++) {
        const long long i = (long long)i0 + (long long)k * STRIDE;
        if (i < N_VEC4) {
            if (i >= DELAY_VEC4) {
                v[k] = ldg_hint(chunk4 + (i - DELAY_VEC4), pol);
            } else {
                v[k] = make_float4(0.f, 0.f, 0.f, 0.f);
            }
        }
    }

#pragma unroll
    for (int k = 0; k < ITERS; k++) {
        const long long i = (long long)i0 + (long long)k * STRIDE;
        if (i < N_VEC4) {
            float4 o;
            o.x = v[k].x * w.x;
            o.y = v[k].y * w.y;
            o.z = v[k].z * w.z;
            o.w = v[k].w * w.w;
            stg_hint(out4 + i, o, pol);
        }
    }
}

extern "C" void kernel_launch(void* const* d_in, const int* in_sizes, int n_in,
                              void* d_out, int out_size)
{
    const float4* chunk4 = reinterpret_cast<const float4*>(d_in[0]);
    const float*  aw     = reinterpret_cast<const float*>(d_in[1]);
    const float*  sw     = reinterpret_cast<const float*>(d_in[2]);
    float4*       out4   = reinterpret_cast<float4*>(d_out);

    stft_delay_scale_kernel<<<BLOCKS, THREADS>>>(chunk4, aw, sw, out4);
}